// round 4
// baseline (speedup 1.0000x reference)
#include <cuda_runtime.h>
#include <math.h>

// Problem constants
#define BB 64      // batch
#define TT 256     // time steps
#define HH 512     // hidden
#define NG 3584    // 7*H gate width
#define KK 512     // per-half K (x part / h part each 512)

typedef unsigned long long u64;

// ---------------- packed fp32x2 helpers (sm_103a FFMA2) ----------------
__device__ __forceinline__ u64 pack2(float x, float y) {
    u64 r; asm("mov.b64 %0,{%1,%2};" : "=l"(r) : "f"(x), "f"(y)); return r;
}
__device__ __forceinline__ void ffma2(u64 &d, u64 a, u64 b) {
    asm("fma.rn.f32x2 %0,%1,%2,%0;" : "+l"(d) : "l"(a), "l"(b));
}
__device__ __forceinline__ void fadd2(u64 &d, u64 a) {
    asm("add.rn.f32x2 %0,%0,%1;" : "+l"(d) : "l"(a));
}
__device__ __forceinline__ float2 unpack2(u64 v) {
    float2 f; asm("mov.b64 {%0,%1},%2;" : "=f"(f.x), "=f"(f.y) : "l"(v)); return f;
}

// ---------------- scratch (no allocations allowed) ----------------
// GX layout: [t][b][n], n = j*512 + c  (x-part pre-activations + bias)
__device__ float g_gx[(long long)BB * TT * NG];   // ~224MB
__device__ unsigned g_bar_count = 0;
__device__ unsigned g_bar_gen = 0;

// ---------------- Phase 1: GX = X @ W[0:512] + b  (M=16384,K=512,N=3584) ----
// 128x128 block tile, 8x8 thread tile, BK=8, 256 threads.
#define BM1 128
#define BN1 128
#define BK1 8

__global__ __launch_bounds__(256) void gemm_gx_kernel(
    const float* __restrict__ X,   // [B*T, 512]
    const float* __restrict__ W,   // [1024, 3584]
    const float* __restrict__ bias,// [3584]
    float* __restrict__ GX)        // [T][B][3584]
{
    __shared__ float As[BK1][BM1 + 4];  // transposed [k][m]
    __shared__ float Bs[BK1][BN1];

    const int tid = threadIdx.x;
    const int bm = blockIdx.y * BM1;
    const int bn = blockIdx.x * BN1;
    const int ty = tid >> 4;        // 0..15 -> 8 rows each
    const int tx = tid & 15;        // 0..15 -> 8 cols each

    const int arow = tid >> 1;            // 0..127
    const int acol = (tid & 1) * 4;       // 0 or 4
    const int brow = tid >> 5;            // 0..7
    const int bcol = (tid & 31) * 4;      // 0..124

    u64 acc[8][4];
#pragma unroll
    for (int i = 0; i < 8; i++)
#pragma unroll
        for (int j = 0; j < 4; j++) acc[i][j] = 0ull;

    for (int k0 = 0; k0 < KK; k0 += BK1) {
        float4 av = *(const float4*)&X[(long long)(bm + arow) * KK + k0 + acol];
        As[acol + 0][arow] = av.x;
        As[acol + 1][arow] = av.y;
        As[acol + 2][arow] = av.z;
        As[acol + 3][arow] = av.w;
        float4 bv = *(const float4*)&W[(long long)(k0 + brow) * NG + bn + bcol];
        *(float4*)&Bs[brow][bcol] = bv;
        __syncthreads();

#pragma unroll
        for (int kk = 0; kk < BK1; kk++) {
            ulonglong2 b01 = *(const ulonglong2*)&Bs[kk][tx * 8];
            ulonglong2 b23 = *(const ulonglong2*)&Bs[kk][tx * 8 + 4];
#pragma unroll
            for (int i = 0; i < 8; i++) {
                float a = As[kk][ty * 8 + i];
                u64 a2 = pack2(a, a);
                ffma2(acc[i][0], a2, b01.x);
                ffma2(acc[i][1], a2, b01.y);
                ffma2(acc[i][2], a2, b23.x);
                ffma2(acc[i][3], a2, b23.y);
            }
        }
        __syncthreads();
    }

    const int n = bn + tx * 8;
    float bv0 = bias[n + 0], bv1 = bias[n + 1], bv2 = bias[n + 2], bv3 = bias[n + 3];
    float bv4 = bias[n + 4], bv5 = bias[n + 5], bv6 = bias[n + 6], bv7 = bias[n + 7];
#pragma unroll
    for (int i = 0; i < 8; i++) {
        const int m = bm + ty * 8 + i;
        const int b = m >> 8;        // m = b*TT + t
        const int t = m & 255;
        float* row = &GX[((long long)t * BB + b) * NG + n];
        float2 r0 = unpack2(acc[i][0]);
        float2 r1 = unpack2(acc[i][1]);
        float2 r2 = unpack2(acc[i][2]);
        float2 r3 = unpack2(acc[i][3]);
        float4 o0 = make_float4(r0.x + bv0, r0.y + bv1, r1.x + bv2, r1.y + bv3);
        float4 o1 = make_float4(r2.x + bv4, r2.y + bv5, r3.x + bv6, r3.y + bv7);
        *(float4*)&row[0] = o0;
        *(float4*)&row[4] = o1;
    }
}

// ---------------- Phase 2: persistent scan kernel ----------------
// 128 CTAs x 512 threads. CTA blk owns h-columns [blk*4, blk*4+4).
// tid: ks = tid>>8 (K half), r = tid&255, b = r>>2, cc = r&3.
// Each (b,cc) pair of threads K-splits the 512-deep dot products, then
// combines via SMEM. ks==0 threads finish the cell math.
// SMEM: Ws [512][32] (28 gate cols padded to 32, layout k*32 + cc*8 + j)
//       hs [64][516] (h_{t-1} staged; reused as the K-split exchange buffer)

#define NBLK 128
#define HS_STRIDE 516
#define WS_FLOATS (KK * 32)
#define SMEM_BYTES ((WS_FLOATS + BB * HS_STRIDE) * 4)

__device__ __forceinline__ void grid_barrier() {
    __threadfence();
    __syncthreads();
    if (threadIdx.x == 0) {
        unsigned gen = *(volatile unsigned*)&g_bar_gen;
        unsigned arrived = atomicAdd(&g_bar_count, 1u);
        if (arrived == NBLK - 1) {
            g_bar_count = 0;
            __threadfence();
            *(volatile unsigned*)&g_bar_gen = gen + 1;
        } else {
            while (*(volatile unsigned*)&g_bar_gen == gen) {}
        }
    }
    __syncthreads();
}

__device__ __forceinline__ float sigmoidf_(float x) {
    return 1.f / (1.f + expf(-x));
}
__device__ __forceinline__ float softplusf_(float x) {
    return fmaxf(x, 0.f) + log1pf(expf(-fabsf(x)));
}

__global__ __launch_bounds__(512, 1) void scan_kernel(
    const float* __restrict__ GX,    // [T][B][3584]
    const float* __restrict__ dtime, // [B,T]
    const float* __restrict__ W,     // [1024, 3584]
    float* out)                      // h_ts[B,T,H] then decay[B,T,4,H]
{
    extern __shared__ float smem[];
    float* Ws = smem;                  // [512][32]
    float* hs = smem + WS_FLOATS;      // [64][516]; reused as exchange buffer

    const int tid = threadIdx.x;
    const int blk = blockIdx.x;
    const int c0 = blk * 4;
    const int ks = tid >> 8;          // 0 or 1 (K half)
    const int r  = tid & 255;
    const int b  = r >> 2;
    const int cc = r & 3;
    const int c  = c0 + cc;

    // One-time: load this CTA's W_h slice into SMEM.
    // Ws[k*32 + cc2*8 + j] = W[(512+k)][j*512 + c0 + cc2], j<7; j==7 slot = 0
    for (int i = tid; i < WS_FLOATS; i += 512) {
        int k = i >> 5;
        int rr = i & 31;
        int cc2 = rr >> 3;
        int j = rr & 7;
        float v = 0.f;
        if (j < 7) v = W[(long long)(KK + k) * NG + j * HH + c0 + cc2];
        Ws[i] = v;
    }
    __syncthreads();

    float cf_r = 0.f;   // c_func state for (b, c)   [only used by ks==0]
    float cb_r = 0.f;   // c_bar state

    const u64* Ws8base = (const u64*)Ws + cc * 4;
    const float* hrow = hs + b * HS_STRIDE + ks * 256;
    const long long DEC0 = (long long)BB * TT * HH;

    for (int t = 0; t < TT; t++) {
        // x-part gate values (independent of h; issue early)
        float x0, x1, x2, x3, x4, x5, x6, dt;
        if (ks == 0) {
            const float* gx = GX + ((long long)t * BB + b) * NG + c;
            x0 = gx[0 * HH];
            x1 = gx[1 * HH];
            x2 = gx[2 * HH];
            x3 = gx[3 * HH];
            x4 = gx[4 * HH];
            x5 = gx[5 * HH];
            x6 = gx[6 * HH];
            dt = dtime[b * TT + t];
        }

        u64 acc0 = 0ull, acc1 = 0ull, acc2 = 0ull, acc3 = 0ull;

        if (t > 0) {
            // stage h_{t-1} into SMEM: 64 rows x 512 floats (float4 x 8192 / 512 thr)
#pragma unroll
            for (int i = 0; i < 16; i++) {
                int lin = i * 512 + tid;        // float4 index 0..8191
                int bb = lin >> 7;
                int q = lin & 127;
                float4 v = *(const float4*)&out[((long long)bb * TT + (t - 1)) * HH + q * 4];
                *(float4*)&hs[bb * HS_STRIDE + q * 4] = v;
            }
            __syncthreads();

            // Half the dot product per thread (k in [ks*256, ks*256+256))
            const u64* wr = Ws8base + ((ks * 256) << 4);
#pragma unroll 4
            for (int k = 0; k < 256; k++) {
                float a = hrow[k];
                u64 a2 = pack2(a, a);
                ulonglong2 w01 = *(const ulonglong2*)(wr);
                ulonglong2 w23 = *(const ulonglong2*)(wr + 2);
                wr += 16;
                ffma2(acc0, a2, w01.x);
                ffma2(acc1, a2, w01.y);
                ffma2(acc2, a2, w23.x);
                ffma2(acc3, a2, w23.y);
            }

            // combine K-halves through SMEM (reuse hs region)
            __syncthreads();                 // everyone done reading hs
            u64* xchg = (u64*)hs;
            if (ks == 1) {
                ulonglong2* p = (ulonglong2*)(xchg + r * 4);
                p[0] = make_ulonglong2(acc0, acc1);
                p[1] = make_ulonglong2(acc2, acc3);
            }
            __syncthreads();
            if (ks == 0) {
                const ulonglong2* p = (const ulonglong2*)(xchg + r * 4);
                ulonglong2 q0 = p[0];
                ulonglong2 q1 = p[1];
                fadd2(acc0, q0.x);
                fadd2(acc1, q0.y);
                fadd2(acc2, q1.x);
                fadd2(acc3, q1.y);
            }
        }

        if (ks == 0) {
            float2 p01 = unpack2(acc0);
            float2 p23 = unpack2(acc1);
            float2 p45 = unpack2(acc2);
            float2 p6x = unpack2(acc3);

            const float g0 = x0 + p01.x;
            const float g1 = x1 + p01.y;
            const float g2 = x2 + p23.x;
            const float g3 = x3 + p23.y;
            const float g4 = x4 + p45.x;
            const float g5 = x5 + p45.y;
            const float g6 = x6 + p6x.x;

            const float gate_i  = sigmoidf_(g0);
            const float gate_f  = sigmoidf_(g1);
            const float gate_o  = sigmoidf_(g2);
            const float gate_ib = sigmoidf_(g3);
            const float gate_fb = sigmoidf_(g4);
            const float gate_d  = softplusf_(g5);
            const float z       = tanhf(g6);

            const float c_t  = gate_f  * cf_r + gate_i  * z;
            const float cb_t = gate_fb * cb_r + gate_ib * z;
            const float cfn  = cb_t + (c_t - cb_t) * expf(-gate_d * dt);
            const float h_t  = gate_o * tanhf(cfn);

            cf_r = cfn;
            cb_r = cb_t;

            // h_ts[b][t][c]
            out[((long long)b * TT + t) * HH + c] = h_t;
            // decay_states[b][t][s][c]
            float* dec = out + DEC0 + ((long long)(b * TT + t) * 4) * HH + c;
            dec[0 * HH] = c_t;
            dec[1 * HH] = cb_t;
            dec[2 * HH] = gate_d;
            dec[3 * HH] = gate_o;
        }

        // make h_t visible chip-wide before anyone reads step t
        grid_barrier();
    }
}

// ---------------- launch ----------------
extern "C" void kernel_launch(void* const* d_in, const int* in_sizes, int n_in,
                              void* d_out, int out_size) {
    (void)in_sizes; (void)n_in; (void)out_size;
    const float* X     = (const float*)d_in[0];  // seq_type_embed [B,T,H]
    const float* dtime = (const float*)d_in[1];  // [B,T]
    const float* W     = (const float*)d_in[2];  // [2H, 7H]
    const float* bias  = (const float*)d_in[3];  // [7H]
    float* out = (float*)d_out;

    float* GX;
    cudaGetSymbolAddress((void**)&GX, g_gx);

    // Phase 1: precompute x-part pre-activations for all timesteps
    dim3 grid1(NG / BN1, (BB * TT) / BM1);   // (28, 128)
    gemm_gx_kernel<<<grid1, 256>>>(X, W, bias, GX);

    // Phase 2: one persistent kernel for the whole scan
    cudaFuncSetAttribute(scan_kernel, cudaFuncAttributeMaxDynamicSharedMemorySize,
                         SMEM_BYTES);
    scan_kernel<<<NBLK, 512, SMEM_BYTES>>>(GX, dtime, W, out);
}

// round 6
// speedup vs baseline: 1.9012x; 1.9012x over previous
#include <cuda_runtime.h>
#include <math.h>

// Problem constants
#define BB 64      // batch
#define TT 256     // time steps
#define HH 512     // hidden
#define NG 3584    // 7*H gate width
#define KK 512     // per-half K (x part / h part each 512)

typedef unsigned long long u64;
typedef unsigned int u32;

// ---------------- packed fp32x2 helpers (sm_103a FFMA2) ----------------
__device__ __forceinline__ u64 pack2(float x, float y) {
    u64 r; asm("mov.b64 %0,{%1,%2};" : "=l"(r) : "f"(x), "f"(y)); return r;
}
__device__ __forceinline__ void ffma2(u64 &d, u64 a, u64 b) {
    asm("fma.rn.f32x2 %0,%1,%2,%0;" : "+l"(d) : "l"(a), "l"(b));
}
__device__ __forceinline__ float2 unpack2(u64 v) {
    float2 f; asm("mov.b64 {%0,%1},%2;" : "=f"(f.x), "=f"(f.y) : "l"(v)); return f;
}

// ---------------- tf32 mma helpers ----------------
__device__ __forceinline__ u32 f2tf32(float f) {
    u32 u; asm("cvt.rna.tf32.f32 %0, %1;" : "=r"(u) : "f"(f)); return u;
}
__device__ __forceinline__ void mma_tf32(float &c0, float &c1, float &c2, float &c3,
                                         u32 a0, u32 a1, u32 a2, u32 a3,
                                         u32 b0, u32 b1) {
    asm("mma.sync.aligned.m16n8k8.row.col.f32.tf32.tf32.f32 "
        "{%0,%1,%2,%3},{%4,%5,%6,%7},{%8,%9},{%0,%1,%2,%3};"
        : "+f"(c0), "+f"(c1), "+f"(c2), "+f"(c3)
        : "r"(a0), "r"(a1), "r"(a2), "r"(a3), "r"(b0), "r"(b1));
}

// ---------------- scratch (no allocations allowed) ----------------
// GX layout: [t][b][n], n = j*512 + c  (x-part pre-activations + bias)
__device__ float g_gx[(long long)BB * TT * NG];   // ~224MB
__device__ u32 g_bar_count = 0;
__device__ u32 g_bar_gen = 0;

// ---------------- Phase 1: GX = X @ W[0:512] + b  (unchanged, FFMA2) -------
#define BM1 128
#define BN1 128
#define BK1 8

__global__ __launch_bounds__(256) void gemm_gx_kernel(
    const float* __restrict__ X,   // [B*T, 512]
    const float* __restrict__ W,   // [1024, 3584]
    const float* __restrict__ bias,// [3584]
    float* __restrict__ GX)        // [T][B][3584]
{
    __shared__ float As[BK1][BM1 + 4];
    __shared__ float Bs[BK1][BN1];

    const int tid = threadIdx.x;
    const int bm = blockIdx.y * BM1;
    const int bn = blockIdx.x * BN1;
    const int ty = tid >> 4;
    const int tx = tid & 15;

    const int arow = tid >> 1;
    const int acol = (tid & 1) * 4;
    const int brow = tid >> 5;
    const int bcol = (tid & 31) * 4;

    u64 acc[8][4];
#pragma unroll
    for (int i = 0; i < 8; i++)
#pragma unroll
        for (int j = 0; j < 4; j++) acc[i][j] = 0ull;

    for (int k0 = 0; k0 < KK; k0 += BK1) {
        float4 av = *(const float4*)&X[(long long)(bm + arow) * KK + k0 + acol];
        As[acol + 0][arow] = av.x;
        As[acol + 1][arow] = av.y;
        As[acol + 2][arow] = av.z;
        As[acol + 3][arow] = av.w;
        float4 bv = *(const float4*)&W[(long long)(k0 + brow) * NG + bn + bcol];
        *(float4*)&Bs[brow][bcol] = bv;
        __syncthreads();

#pragma unroll
        for (int kk = 0; kk < BK1; kk++) {
            ulonglong2 b01 = *(const ulonglong2*)&Bs[kk][tx * 8];
            ulonglong2 b23 = *(const ulonglong2*)&Bs[kk][tx * 8 + 4];
#pragma unroll
            for (int i = 0; i < 8; i++) {
                float a = As[kk][ty * 8 + i];
                u64 a2 = pack2(a, a);
                ffma2(acc[i][0], a2, b01.x);
                ffma2(acc[i][1], a2, b01.y);
                ffma2(acc[i][2], a2, b23.x);
                ffma2(acc[i][3], a2, b23.y);
            }
        }
        __syncthreads();
    }

    const int n = bn + tx * 8;
    float bv0 = bias[n + 0], bv1 = bias[n + 1], bv2 = bias[n + 2], bv3 = bias[n + 3];
    float bv4 = bias[n + 4], bv5 = bias[n + 5], bv6 = bias[n + 6], bv7 = bias[n + 7];
#pragma unroll
    for (int i = 0; i < 8; i++) {
        const int m = bm + ty * 8 + i;
        const int b = m >> 8;        // m = b*TT + t
        const int t = m & 255;
        float* row = &GX[((long long)t * BB + b) * NG + n];
        float2 r0 = unpack2(acc[i][0]);
        float2 r1 = unpack2(acc[i][1]);
        float2 r2 = unpack2(acc[i][2]);
        float2 r3 = unpack2(acc[i][3]);
        float4 o0 = make_float4(r0.x + bv0, r0.y + bv1, r1.x + bv2, r1.y + bv3);
        float4 o1 = make_float4(r2.x + bv4, r2.y + bv5, r3.x + bv6, r3.y + bv7);
        *(float4*)&row[0] = o0;
        *(float4*)&row[4] = o1;
    }
}

// ---------------- Phase 2: persistent scan with tf32 mma ----------------
// 128 CTAs x 512 threads (16 warps). CTA blk owns h-columns [blk*4, blk*4+4).
// Virtual N = 32: v = cc*8 + j (cc = h-col within slice, j = gate, j==7 pad).
// Warp w: m-tile mt = w&3 (16 batch rows), n-tile nt = w>>2 (== cc).
// k-loop: 64 steps of m16n8k8 tf32 mma.
// SMEM: Ws  [4][64][64] u32 tf32 W_h fragments in exact lane order (64KB)
//       hs  [64][516]   u32 tf32 h_{t-1} staged per step (132KB)
//       gh  [64][34]    fp32 epilogue exchange (8.7KB)

#define NBLK 128
#define HS_STRIDE 516
#define WS_U32 (4 * 64 * 64)        // 16384
#define HS_U32 (BB * HS_STRIDE)     // 33024
#define GH_STRIDE 34
#define GH_F32 (BB * GH_STRIDE)     // 2176
#define SMEM_BYTES ((WS_U32 + HS_U32 + GH_F32) * 4)

__device__ __forceinline__ void grid_barrier() {
    __syncthreads();
    if (threadIdx.x == 0) {
        u32 gen;
        asm volatile("ld.relaxed.gpu.u32 %0, [%1];" : "=r"(gen) : "l"(&g_bar_gen) : "memory");
        u32 old;
        asm volatile("atom.add.acq_rel.gpu.u32 %0, [%1], 1;" : "=r"(old) : "l"(&g_bar_count) : "memory");
        if (old == NBLK - 1) {
            asm volatile("st.relaxed.gpu.u32 [%0], 0;" :: "l"(&g_bar_count) : "memory");
            u32 ng = gen + 1;
            asm volatile("st.release.gpu.u32 [%0], %1;" :: "l"(&g_bar_gen), "r"(ng) : "memory");
        } else {
            u32 cur;
            do {
                asm volatile("ld.acquire.gpu.u32 %0, [%1];" : "=r"(cur) : "l"(&g_bar_gen) : "memory");
            } while (cur == gen);
        }
    }
    __syncthreads();
}

__device__ __forceinline__ float sigmoidf_(float x) {
    return 1.f / (1.f + expf(-x));
}
__device__ __forceinline__ float softplusf_(float x) {
    return fmaxf(x, 0.f) + log1pf(expf(-fabsf(x)));
}

__global__ __launch_bounds__(512, 1) void scan_kernel(
    const float* __restrict__ GX,    // [T][B][3584]
    const float* __restrict__ dtime, // [B,T]
    const float* __restrict__ W,     // [1024, 3584]
    float* out)                      // h_ts[B,T,H] then decay[B,T,4,H]
{
    extern __shared__ u32 smem_u[];
    u32* Ws = smem_u;                       // [4][64][64]
    u32* hs = smem_u + WS_U32;              // [64][516]
    float* gh = (float*)(smem_u + WS_U32 + HS_U32);  // [64][34]

    const int tid = threadIdx.x;
    const int blk = blockIdx.x;
    const int c0 = blk * 4;

    const int w = tid >> 5;          // warp 0..15
    const int l = tid & 31;          // lane
    const int mt = w & 3;            // m-tile (batch rows mt*16..+15)
    const int nt = w >> 2;           // n-tile == cc (h-col within slice)
    const int m0 = mt * 16;
    const int g = l >> 2;            // group id
    const int tk = l & 3;            // thread-in-group

    // cell-math thread mapping (threads 0..255)
    const int r = tid & 255;
    const int b = r >> 2;
    const int cc = r & 3;
    const int c = c0 + cc;

    // ---- one-time init: W_h fragments (tf32, lane order) + zero gh ----
    // Ws idx = ((nt2*64 + ks)*64) + l2*2 + slot:
    //   value = W_h[k = ks*8 + (l2&3) + slot*4][gate j = l2>>2, h-col c0+nt2]
    for (int i = tid; i < WS_U32; i += 512) {
        int slot = i & 1;
        int l2 = (i >> 1) & 31;
        int ks = (i >> 6) & 63;
        int nt2 = i >> 12;
        int k = ks * 8 + (l2 & 3) + slot * 4;
        int j = l2 >> 2;
        float v = 0.f;
        if (j < 7) v = W[(long long)(KK + k) * NG + j * HH + c0 + nt2];
        Ws[i] = f2tf32(v);
    }
    for (int i = tid; i < GH_F32; i += 512) gh[i] = 0.f;
    __syncthreads();

    float cf_r = 0.f;   // cell state for (b, c), threads r<256
    float cb_r = 0.f;

    // fragment base pointers
    const u32* hA0 = hs + (m0 + g) * HS_STRIDE + tk;
    const u32* hA1 = hs + (m0 + g + 8) * HS_STRIDE + tk;
    const u32* wB  = Ws + nt * 64 * 64 + l * 2;
    const long long DEC0 = (long long)BB * TT * HH;

    for (int t = 0; t < TT; t++) {
        // x-part gate values + dt (independent of h; issue early)
        float x0, x1, x2, x3, x4, x5, x6, dt;
        if (tid < 256) {
            const float* gx = GX + ((long long)t * BB + b) * NG + c;
            x0 = gx[0 * HH];
            x1 = gx[1 * HH];
            x2 = gx[2 * HH];
            x3 = gx[3 * HH];
            x4 = gx[4 * HH];
            x5 = gx[5 * HH];
            x6 = gx[6 * HH];
            dt = dtime[b * TT + t];
        }

        if (t > 0) {
            // stage h_{t-1} -> SMEM, converting to tf32 (8192 float4 / 512 thr)
#pragma unroll
            for (int i = 0; i < 16; i++) {
                int lin = i * 512 + tid;
                int bb = lin >> 7;
                int q = lin & 127;
                float4 v = *(const float4*)&out[((long long)bb * TT + (t - 1)) * HH + q * 4];
                uint4 u;
                u.x = f2tf32(v.x);
                u.y = f2tf32(v.y);
                u.z = f2tf32(v.z);
                u.w = f2tf32(v.w);
                *(uint4*)&hs[bb * HS_STRIDE + q * 4] = u;
            }
            __syncthreads();

            // 16x8 output tile per warp: 64 k-steps of m16n8k8 tf32
            float acc0 = 0.f, acc1 = 0.f, acc2 = 0.f, acc3 = 0.f;
#pragma unroll 8
            for (int ks = 0; ks < 64; ks++) {
                u32 a0 = hA0[ks * 8];
                u32 a2 = hA0[ks * 8 + 4];
                u32 a1 = hA1[ks * 8];
                u32 a3 = hA1[ks * 8 + 4];
                uint2 bfr = *(const uint2*)(wB + ks * 64);
                mma_tf32(acc0, acc1, acc2, acc3, a0, a1, a2, a3, bfr.x, bfr.y);
            }

            // epilogue: C frags -> gh[64][34]
            __syncthreads();   // all hs reads done (gh shares no space, but order C writes after everyone's mma reads of previous gh consumers is handled by the barrier; this sync orders gh writes below vs reads above across warps)
            const int col = nt * 8 + tk * 2;
            *(float2*)&gh[(m0 + g) * GH_STRIDE + col] = make_float2(acc0, acc1);
            *(float2*)&gh[(m0 + g + 8) * GH_STRIDE + col] = make_float2(acc2, acc3);
            __syncthreads();
        }

        if (tid < 256) {
            const float* ghr = &gh[b * GH_STRIDE + cc * 8];
            const float g0 = x0 + ghr[0];
            const float g1 = x1 + ghr[1];
            const float g2 = x2 + ghr[2];
            const float g3 = x3 + ghr[3];
            const float g4 = x4 + ghr[4];
            const float g5 = x5 + ghr[5];
            const float g6 = x6 + ghr[6];

            const float gate_i  = sigmoidf_(g0);
            const float gate_f  = sigmoidf_(g1);
            const float gate_o  = sigmoidf_(g2);
            const float gate_ib = sigmoidf_(g3);
            const float gate_fb = sigmoidf_(g4);
            const float gate_d  = softplusf_(g5);
            const float z       = tanhf(g6);

            const float c_t  = gate_f  * cf_r + gate_i  * z;
            const float cb_t = gate_fb * cb_r + gate_ib * z;
            const float cfn  = cb_t + (c_t - cb_t) * expf(-gate_d * dt);
            const float h_t  = gate_o * tanhf(cfn);

            cf_r = cfn;
            cb_r = cb_t;

            out[((long long)b * TT + t) * HH + c] = h_t;
            float* dec = out + DEC0 + ((long long)(b * TT + t) * 4) * HH + c;
            dec[0 * HH] = c_t;
            dec[1 * HH] = cb_t;
            dec[2 * HH] = gate_d;
            dec[3 * HH] = gate_o;
        }

        // make h_t visible chip-wide before anyone stages step t+1
        grid_barrier();
    }
}

// ---------------- launch ----------------
extern "C" void kernel_launch(void* const* d_in, const int* in_sizes, int n_in,
                              void* d_out, int out_size) {
    (void)in_sizes; (void)n_in; (void)out_size;
    const float* X     = (const float*)d_in[0];  // seq_type_embed [B,T,H]
    const float* dtime = (const float*)d_in[1];  // [B,T]
    const float* W     = (const float*)d_in[2];  // [2H, 7H]
    const float* bias  = (const float*)d_in[3];  // [7H]
    float* out = (float*)d_out;

    float* GX;
    cudaGetSymbolAddress((void**)&GX, g_gx);

    // Phase 1: precompute x-part pre-activations for all timesteps
    dim3 grid1(NG / BN1, (BB * TT) / BM1);   // (28, 128)
    gemm_gx_kernel<<<grid1, 256>>>(X, W, bias, GX);

    // Phase 2: one persistent kernel for the whole scan
    cudaFuncSetAttribute(scan_kernel, cudaFuncAttributeMaxDynamicSharedMemorySize,
                         SMEM_BYTES);
    scan_kernel<<<NBLK, 512, SMEM_BYTES>>>(GX, dtime, W, out);
}

// round 7
// speedup vs baseline: 2.3495x; 1.2358x over previous
#include <cuda_runtime.h>
#include <math.h>

// Problem constants
#define BB 64      // batch
#define TT 256     // time steps
#define HH 512     // hidden
#define NG 3584    // 7*H gate width
#define KK 512     // per-half K (x part / h part each 512)

typedef unsigned long long u64;
typedef unsigned int u32;

// ---------------- tf32 mma helpers ----------------
__device__ __forceinline__ u32 f2tf32(float f) {
    u32 u; asm("cvt.rna.tf32.f32 %0, %1;" : "=r"(u) : "f"(f)); return u;
}
__device__ __forceinline__ void mma_tf32(float &c0, float &c1, float &c2, float &c3,
                                         u32 a0, u32 a1, u32 a2, u32 a3,
                                         u32 b0, u32 b1) {
    asm("mma.sync.aligned.m16n8k8.row.col.f32.tf32.tf32.f32 "
        "{%0,%1,%2,%3},{%4,%5,%6,%7},{%8,%9},{%0,%1,%2,%3};"
        : "+f"(c0), "+f"(c1), "+f"(c2), "+f"(c3)
        : "r"(a0), "r"(a1), "r"(a2), "r"(a3), "r"(b0), "r"(b1));
}

// ---------------- scratch (no allocations allowed) ----------------
// GX layout: [t][b][n], n = j*512 + c  (x-part pre-activations + bias)
__device__ float g_gx[(long long)BB * TT * NG];   // ~224MB
__device__ u32 g_bar_count = 0;
__device__ u32 g_bar_gen = 0;

// ---------------- Phase 1: GX = X @ W[0:512] + b  via tf32 mma -------------
// 128x128 block tile, BK=16, 256 threads (8 warps, 2x4), warp tile 64x32.
#define TBM 128
#define TBN 128
#define TBK 16
#define ASTRIDE 20      // As [m][16+4]
#define BSTRIDE 136     // Bs [k][128+8]  (bank = tk*8+g, conflict-free frags)
#define NIT (KK / TBK)  // 32

__global__ __launch_bounds__(256, 1) void gemm_gx_tf32(
    const float* __restrict__ X,   // [B*T, 512]
    const float* __restrict__ W,   // [1024, 3584]
    const float* __restrict__ bias,// [3584]
    float* __restrict__ GX)        // [T][B][3584]
{
    __shared__ u32 As[TBM * ASTRIDE];
    __shared__ u32 Bs[TBK * BSTRIDE];

    const int tid = threadIdx.x;
    const int bm = blockIdx.y * TBM;
    const int bn = blockIdx.x * TBN;
    const int w = tid >> 5, l = tid & 31;
    const int wr = w >> 2, wc = w & 3;
    const int m0w = wr * 64, n0w = wc * 32;
    const int g = l >> 2, tk = l & 3;

    // gmem load maps
    const int arow = tid >> 1;            // 0..127
    const int acol = (tid & 1) * 8;       // 0 or 8
    const int brow = tid >> 4;            // 0..15
    const int bcol = (tid & 15) * 4;      // 0..60

    const float* Aptr = X + (long long)(bm + arow) * KK + acol;
    const float* Bptr = W + (long long)brow * NG + bn + bcol;

    float4 ra0 = *(const float4*)(Aptr);
    float4 ra1 = *(const float4*)(Aptr + 4);
    float4 rb0 = *(const float4*)(Bptr);
    float4 rb1 = *(const float4*)(Bptr + 64);

    float acc[4][4][4];
#pragma unroll
    for (int mi = 0; mi < 4; mi++)
#pragma unroll
        for (int ni = 0; ni < 4; ni++)
#pragma unroll
            for (int q = 0; q < 4; q++) acc[mi][ni][q] = 0.f;

    for (int it = 0; it < NIT; it++) {
        // store current tile (convert to tf32)
        u32* as = &As[arow * ASTRIDE + acol];
        as[0] = f2tf32(ra0.x); as[1] = f2tf32(ra0.y);
        as[2] = f2tf32(ra0.z); as[3] = f2tf32(ra0.w);
        as[4] = f2tf32(ra1.x); as[5] = f2tf32(ra1.y);
        as[6] = f2tf32(ra1.z); as[7] = f2tf32(ra1.w);
        u32* bs = &Bs[brow * BSTRIDE + bcol];
        bs[0] = f2tf32(rb0.x); bs[1] = f2tf32(rb0.y);
        bs[2] = f2tf32(rb0.z); bs[3] = f2tf32(rb0.w);
        bs[64] = f2tf32(rb1.x); bs[65] = f2tf32(rb1.y);
        bs[66] = f2tf32(rb1.z); bs[67] = f2tf32(rb1.w);
        __syncthreads();

        // prefetch next tile (LDG in flight during compute)
        if (it < NIT - 1) {
            const float* An = Aptr + (it + 1) * TBK;
            const float* Bn = Bptr + (long long)(it + 1) * TBK * NG;
            ra0 = *(const float4*)(An);
            ra1 = *(const float4*)(An + 4);
            rb0 = *(const float4*)(Bn);
            rb1 = *(const float4*)(Bn + 64);
        }

#pragma unroll
        for (int kc = 0; kc < 2; kc++) {
            const int kb = kc * 8;
            u32 af[4][4];
#pragma unroll
            for (int mi = 0; mi < 4; mi++) {
                const u32* ap0 = &As[(m0w + mi * 16 + g) * ASTRIDE + kb + tk];
                const u32* ap1 = &As[(m0w + mi * 16 + g + 8) * ASTRIDE + kb + tk];
                af[mi][0] = ap0[0];
                af[mi][1] = ap1[0];
                af[mi][2] = ap0[4];
                af[mi][3] = ap1[4];
            }
            u32 bf[4][2];
#pragma unroll
            for (int ni = 0; ni < 4; ni++) {
                const u32* bp = &Bs[(kb + tk) * BSTRIDE + n0w + ni * 8 + g];
                bf[ni][0] = bp[0];
                bf[ni][1] = bp[4 * BSTRIDE];
            }
#pragma unroll
            for (int mi = 0; mi < 4; mi++)
#pragma unroll
                for (int ni = 0; ni < 4; ni++)
                    mma_tf32(acc[mi][ni][0], acc[mi][ni][1], acc[mi][ni][2], acc[mi][ni][3],
                             af[mi][0], af[mi][1], af[mi][2], af[mi][3],
                             bf[ni][0], bf[ni][1]);
        }
        __syncthreads();
    }

    // epilogue: add bias, write to GX[t][b][n]
#pragma unroll
    for (int ni = 0; ni < 4; ni++) {
        const int n = bn + n0w + ni * 8 + tk * 2;
        const float2 bv = *(const float2*)&bias[n];
#pragma unroll
        for (int mi = 0; mi < 4; mi++) {
            const int mA = bm + m0w + mi * 16 + g;
            const int mB = mA + 8;
            const int bA = mA >> 8, tA = mA & 255;
            const int bA2 = mB >> 8, tB = mB & 255;
            float2 o0 = make_float2(acc[mi][ni][0] + bv.x, acc[mi][ni][1] + bv.y);
            float2 o1 = make_float2(acc[mi][ni][2] + bv.x, acc[mi][ni][3] + bv.y);
            *(float2*)&GX[((long long)tA * BB + bA) * NG + n] = o0;
            *(float2*)&GX[((long long)tB * BB + bA2) * NG + n] = o1;
        }
    }
}

// ---------------- Phase 2: persistent scan with tf32 mma ----------------
// 128 CTAs x 512 threads (16 warps). CTA blk owns h-columns [blk*4, blk*4+4).
// Virtual N = 32: v = cc*8 + j (cc = h-col within slice, j = gate, j==7 pad).
// Warp w: m-tile mt = w&3 (16 batch rows), n-tile nt = w>>2 (== cc).
// SMEM: Ws  [4][64][64] u32 tf32 W_h fragments in exact lane order
//       hs  [64][516]   u32 tf32 h_{t-1} staged per step
//       gh  [64][34]    fp32 epilogue exchange

#define NBLK 128
#define HS_STRIDE 516
#define WS_U32 (4 * 64 * 64)        // 16384
#define HS_U32 (BB * HS_STRIDE)     // 33024
#define GH_STRIDE 34
#define GH_F32 (BB * GH_STRIDE)     // 2176
#define SMEM_BYTES ((WS_U32 + HS_U32 + GH_F32) * 4)

__device__ __forceinline__ void grid_barrier() {
    __syncthreads();
    if (threadIdx.x == 0) {
        u32 gen;
        asm volatile("ld.relaxed.gpu.u32 %0, [%1];" : "=r"(gen) : "l"(&g_bar_gen) : "memory");
        u32 old;
        asm volatile("atom.add.acq_rel.gpu.u32 %0, [%1], 1;" : "=r"(old) : "l"(&g_bar_count) : "memory");
        if (old == NBLK - 1) {
            asm volatile("st.relaxed.gpu.u32 [%0], 0;" :: "l"(&g_bar_count) : "memory");
            u32 ng = gen + 1;
            asm volatile("st.release.gpu.u32 [%0], %1;" :: "l"(&g_bar_gen), "r"(ng) : "memory");
        } else {
            u32 cur;
            do {
                asm volatile("ld.acquire.gpu.u32 %0, [%1];" : "=r"(cur) : "l"(&g_bar_gen) : "memory");
            } while (cur == gen);
        }
    }
    __syncthreads();
}

__device__ __forceinline__ float sigmoidf_(float x) {
    return 1.f / (1.f + expf(-x));
}
__device__ __forceinline__ float softplusf_(float x) {
    return fmaxf(x, 0.f) + log1pf(expf(-fabsf(x)));
}

__global__ __launch_bounds__(512, 1) void scan_kernel(
    const float* __restrict__ GX,    // [T][B][3584]
    const float* __restrict__ dtime, // [B,T]
    const float* __restrict__ W,     // [1024, 3584]
    float* out)                      // h_ts[B,T,H] then decay[B,T,4,H]
{
    extern __shared__ u32 smem_u[];
    u32* Ws = smem_u;                       // [4][64][64]
    u32* hs = smem_u + WS_U32;              // [64][516]
    float* gh = (float*)(smem_u + WS_U32 + HS_U32);  // [64][34]

    const int tid = threadIdx.x;
    const int blk = blockIdx.x;
    const int c0 = blk * 4;

    const int w = tid >> 5;
    const int l = tid & 31;
    const int mt = w & 3;
    const int nt = w >> 2;
    const int m0 = mt * 16;
    const int g = l >> 2;
    const int tk = l & 3;

    const int r = tid & 255;
    const int b = r >> 2;
    const int cc = r & 3;
    const int c = c0 + cc;

    // one-time init: W_h fragments (tf32, lane order) + zero gh
    for (int i = tid; i < WS_U32; i += 512) {
        int slot = i & 1;
        int l2 = (i >> 1) & 31;
        int ks = (i >> 6) & 63;
        int nt2 = i >> 12;
        int k = ks * 8 + (l2 & 3) + slot * 4;
        int j = l2 >> 2;
        float v = 0.f;
        if (j < 7) v = W[(long long)(KK + k) * NG + j * HH + c0 + nt2];
        Ws[i] = f2tf32(v);
    }
    for (int i = tid; i < GH_F32; i += 512) gh[i] = 0.f;
    __syncthreads();

    float cf_r = 0.f;
    float cb_r = 0.f;

    const u32* hA0 = hs + (m0 + g) * HS_STRIDE + tk;
    const u32* hA1 = hs + (m0 + g + 8) * HS_STRIDE + tk;
    const u32* wB  = Ws + nt * 64 * 64 + l * 2;
    const long long DEC0 = (long long)BB * TT * HH;

    for (int t = 0; t < TT; t++) {
        float x0, x1, x2, x3, x4, x5, x6, dt;
        if (tid < 256) {
            const float* gx = GX + ((long long)t * BB + b) * NG + c;
            x0 = gx[0 * HH];
            x1 = gx[1 * HH];
            x2 = gx[2 * HH];
            x3 = gx[3 * HH];
            x4 = gx[4 * HH];
            x5 = gx[5 * HH];
            x6 = gx[6 * HH];
            dt = dtime[b * TT + t];
        }

        if (t > 0) {
            // stage h_{t-1} -> SMEM (tf32)
#pragma unroll
            for (int i = 0; i < 16; i++) {
                int lin = i * 512 + tid;
                int bb = lin >> 7;
                int q = lin & 127;
                float4 v = *(const float4*)&out[((long long)bb * TT + (t - 1)) * HH + q * 4];
                uint4 u;
                u.x = f2tf32(v.x);
                u.y = f2tf32(v.y);
                u.z = f2tf32(v.z);
                u.w = f2tf32(v.w);
                *(uint4*)&hs[bb * HS_STRIDE + q * 4] = u;
            }
            __syncthreads();

            float acc0 = 0.f, acc1 = 0.f, acc2 = 0.f, acc3 = 0.f;
#pragma unroll 8
            for (int ks = 0; ks < 64; ks++) {
                u32 a0 = hA0[ks * 8];
                u32 a2 = hA0[ks * 8 + 4];
                u32 a1 = hA1[ks * 8];
                u32 a3 = hA1[ks * 8 + 4];
                uint2 bfr = *(const uint2*)(wB + ks * 64);
                mma_tf32(acc0, acc1, acc2, acc3, a0, a1, a2, a3, bfr.x, bfr.y);
            }

            // epilogue (no extra sync needed: gh readers of step t-1 are past
            // the grid barrier; gh readers of step t wait on the sync below)
            const int col = nt * 8 + tk * 2;
            *(float2*)&gh[(m0 + g) * GH_STRIDE + col] = make_float2(acc0, acc1);
            *(float2*)&gh[(m0 + g + 8) * GH_STRIDE + col] = make_float2(acc2, acc3);
            __syncthreads();
        }

        if (tid < 256) {
            const float* ghr = &gh[b * GH_STRIDE + cc * 8];
            const float g0 = x0 + ghr[0];
            const float g1 = x1 + ghr[1];
            const float g2 = x2 + ghr[2];
            const float g3 = x3 + ghr[3];
            const float g4 = x4 + ghr[4];
            const float g5 = x5 + ghr[5];
            const float g6 = x6 + ghr[6];

            const float gate_i  = sigmoidf_(g0);
            const float gate_f  = sigmoidf_(g1);
            const float gate_o  = sigmoidf_(g2);
            const float gate_ib = sigmoidf_(g3);
            const float gate_fb = sigmoidf_(g4);
            const float gate_d  = softplusf_(g5);
            const float z       = tanhf(g6);

            const float c_t  = gate_f  * cf_r + gate_i  * z;
            const float cb_t = gate_fb * cb_r + gate_ib * z;
            const float cfn  = cb_t + (c_t - cb_t) * expf(-gate_d * dt);
            const float h_t  = gate_o * tanhf(cfn);

            cf_r = cfn;
            cb_r = cb_t;

            out[((long long)b * TT + t) * HH + c] = h_t;
            float* dec = out + DEC0 + ((long long)(b * TT + t) * 4) * HH + c;
            dec[0 * HH] = c_t;
            dec[1 * HH] = cb_t;
            dec[2 * HH] = gate_d;
            dec[3 * HH] = gate_o;
        }

        grid_barrier();
    }
}

// ---------------- launch ----------------
extern "C" void kernel_launch(void* const* d_in, const int* in_sizes, int n_in,
                              void* d_out, int out_size) {
    (void)in_sizes; (void)n_in; (void)out_size;
    const float* X     = (const float*)d_in[0];  // seq_type_embed [B,T,H]
    const float* dtime = (const float*)d_in[1];  // [B,T]
    const float* W     = (const float*)d_in[2];  // [2H, 7H]
    const float* bias  = (const float*)d_in[3];  // [7H]
    float* out = (float*)d_out;

    float* GX;
    cudaGetSymbolAddress((void**)&GX, g_gx);

    // Phase 1: tf32 mma GEMM for x-part pre-activations
    dim3 grid1(NG / TBN, (BB * TT) / TBM);   // (28, 128)
    gemm_gx_tf32<<<grid1, 256>>>(X, W, bias, GX);

    // Phase 2: one persistent kernel for the whole scan
    cudaFuncSetAttribute(scan_kernel, cudaFuncAttributeMaxDynamicSharedMemorySize,
                         SMEM_BYTES);
    scan_kernel<<<NBLK, 512, SMEM_BYTES>>>(GX, dtime, W, out);
}